// round 7
// baseline (speedup 1.0000x reference)
#include <cuda_runtime.h>
#include <cuda_fp16.h>
#include <cstdint>

#define T2 2048
#define T1 2048
#define EE 512
#define FF 2048
#define NL 4
#define NH 8

// weight-split segment boundaries (floats)
#define WB0 262144     // k_w end
#define WB1 524288     // v_w end
#define WB2 1572864    // sa_q end
#define WB3 2621440    // sa_k end
#define WB4 3670016    // sa_v end
#define WB5 4718592    // sa_o end
#define WB6 5767168    // ca_o end
#define WB7 9961472    // f1 end
#define TOTALW 14155776

// ---------------- scratch (device globals; allocation-free) ----------------
__device__ float g_h   [T2*EE];
__device__ float g_proj[T2*EE];
__device__ float g_op  [2*T2*EE];
__device__ float g_ml  [2*NH*T2*2];
__device__ __half g_hh[T2*EE],   g_hl[T2*EE];
__device__ __half g_qh[T2*EE],   g_ql[T2*EE];
__device__ __half g_kh[T2*EE],   g_kl[T2*EE];
__device__ __half g_vh[T2*EE],   g_vl[T2*EE];
__device__ __half g_atth[T2*EE], g_attl[T2*EE];
__device__ __half g_ffnh[T2*FF], g_ffnl[T2*FF];
__device__ __half g_Ksh[T1*EE],  g_Ksl[T1*EE];
__device__ __half g_Vsh[T1*EE],  g_Vsl[T1*EE];
__device__ __half g_ench[T1*EE], g_encl[T1*EE];
__device__ __half g_wsh[TOTALW], g_wsl[TOTALW];

// ---------------- helpers ----------------
__device__ __forceinline__ void hmma(float* d, const uint32_t* a, const uint32_t* b) {
    asm volatile(
        "mma.sync.aligned.m16n8k16.row.col.f32.f16.f16.f32 "
        "{%0,%1,%2,%3}, {%4,%5,%6,%7}, {%8,%9}, {%0,%1,%2,%3};"
        : "+f"(d[0]), "+f"(d[1]), "+f"(d[2]), "+f"(d[3])
        : "r"(a[0]), "r"(a[1]), "r"(a[2]), "r"(a[3]), "r"(b[0]), "r"(b[1]));
}
#define LDSM4(R, PTR) do {                                                     \
    uint32_t a_ = (uint32_t)__cvta_generic_to_shared(PTR);                     \
    asm volatile("ldmatrix.sync.aligned.m8n8.x4.shared.b16 {%0,%1,%2,%3}, [%4];" \
        : "=r"((R)[0]), "=r"((R)[1]), "=r"((R)[2]), "=r"((R)[3]) : "r"(a_));   \
} while (0)
#define LDSM4T(R, PTR) do {                                                    \
    uint32_t a_ = (uint32_t)__cvta_generic_to_shared(PTR);                     \
    asm volatile("ldmatrix.sync.aligned.m8n8.x4.trans.shared.b16 {%0,%1,%2,%3}, [%4];" \
        : "=r"((R)[0]), "=r"((R)[1]), "=r"((R)[2]), "=r"((R)[3]) : "r"(a_));   \
} while (0)
__device__ __forceinline__ void cp16(uint32_t dst, const void* src) {
    asm volatile("cp.async.cg.shared.global [%0], [%1], 16;"
                 :: "r"(dst), "l"(src) : "memory");
}
__device__ __forceinline__ void cp_commit() {
    asm volatile("cp.async.commit_group;" ::: "memory");
}
#define CP_WAIT1() asm volatile("cp.async.wait_group 1;" ::: "memory")

__device__ __forceinline__ uint32_t packh2(float x, float y) {
    __half2 h = __floats2half2_rn(x, y);
    return *reinterpret_cast<uint32_t*>(&h);
}
// 2-term fp16 split: x ≈ hi + lo to ~2.4e-7 rel.
__device__ __forceinline__ void split2(float x, float y, uint32_t& hi, uint32_t& lo) {
    float hx = __half2float(__float2half_rn(x));
    float hy = __half2float(__float2half_rn(y));
    hi = packh2(hx, hy);
    lo = packh2(x - hx, y - hy);
}

// ---------------- weight pre-split ----------------
__global__ __launch_bounds__(256) void wsplit_kernel(
    const float* __restrict__ k_w, const float* __restrict__ v_w,
    const float* __restrict__ saq, const float* __restrict__ sak,
    const float* __restrict__ sav, const float* __restrict__ sao,
    const float* __restrict__ cao, const float* __restrict__ f1,
    const float* __restrict__ f2, __half* __restrict__ oh, __half* __restrict__ ol)
{
    size_t i4 = ((size_t)blockIdx.x * 256 + threadIdx.x) * 4;
    if (i4 >= TOTALW) return;
    const float* src; size_t loc;
    if      (i4 < WB0) { src = k_w; loc = i4; }
    else if (i4 < WB1) { src = v_w; loc = i4 - WB0; }
    else if (i4 < WB2) { src = saq; loc = i4 - WB1; }
    else if (i4 < WB3) { src = sak; loc = i4 - WB2; }
    else if (i4 < WB4) { src = sav; loc = i4 - WB3; }
    else if (i4 < WB5) { src = sao; loc = i4 - WB4; }
    else if (i4 < WB6) { src = cao; loc = i4 - WB5; }
    else if (i4 < WB7) { src = f1;  loc = i4 - WB6; }
    else               { src = f2;  loc = i4 - WB7; }
    float4 v = *(const float4*)(src + loc);
    uint32_t h01, l01, h23, l23;
    split2(v.x, v.y, h01, l01); split2(v.z, v.w, h23, l23);
    *(uint2*)(oh + i4) = make_uint2(h01, h23);
    *(uint2*)(ol + i4) = make_uint2(l01, l23);
}

// ---------------- copy + split (out32 may be null) ----------------
__global__ void copy_split(const float* __restrict__ in, float* __restrict__ out32,
                           __half* __restrict__ oh, __half* __restrict__ ol) {
    size_t i = ((size_t)blockIdx.x * blockDim.x + threadIdx.x) * 4;
    float4 v = *(const float4*)(in + i);
    if (out32) *(float4*)(out32 + i) = v;
    uint32_t h01, l01, h23, l23;
    split2(v.x, v.y, h01, l01); split2(v.z, v.w, h23, l23);
    *(uint2*)(oh + i) = make_uint2(h01, h23);
    *(uint2*)(ol + i) = make_uint2(l01, l23);
}

__global__ void copyk(const float* __restrict__ in, float* __restrict__ out) {
    size_t i = ((size_t)blockIdx.x * blockDim.x + threadIdx.x) * 4;
    *(float4*)(out + i) = *(const float4*)(in + i);
}

// ---------------- fp16-pair GEMM via cp.async: C = act(A @ B + bias) --------
// Tile 128x64, 256 threads, 8 warps (4x2), warp 32x32, BK=32, 2-stage.
// stage halves: Ah[128][40]@0 Al@5120 Bh[32][72]@10240 Bl@12544; GST=14848.
#define GST 14848
#define GSMEM (2 * GST * 2)   // 59392 B

__global__ __launch_bounds__(256, 2) void gemm_mma(
    const __half* __restrict__ Ah, const __half* __restrict__ Al,
    const __half* __restrict__ Wh, const __half* __restrict__ Wl,
    long boff0, const float* bias0, float* c0, __half* ch0, __half* cl0,
    long boff1, const float* bias1, float* c1, __half* ch1, __half* cl1,
    long boff2, const float* bias2, float* c2, __half* ch2, __half* cl2,
    int N, int K, int act)
{
    extern __shared__ __half hsm[];
    const uint32_t sb = (uint32_t)__cvta_generic_to_shared(hsm);
    const int z = blockIdx.z;
    const long boff       = (z == 0) ? boff0 : ((z == 1) ? boff1 : boff2);
    const float* bias     = (z == 0) ? bias0 : ((z == 1) ? bias1 : bias2);
    float* c32            = (z == 0) ? c0 : ((z == 1) ? c1 : c2);
    __half* ch            = (z == 0) ? ch0 : ((z == 1) ? ch1 : ch2);
    __half* cl            = (z == 0) ? cl0 : ((z == 1) ? cl1 : cl2);
    const __half* Bh = Wh + boff;
    const __half* Bl = Wl + boff;

    const int tid = threadIdx.x;
    const int wid = tid >> 5, lane = tid & 31;
    const int g = lane >> 2, t = lane & 3;
    const int bm = blockIdx.y * 128, bn = blockIdx.x * 64;
    const int wm = (wid >> 1) * 32, wn = (wid & 1) * 32;

    float acc[2][4][4];
    #pragma unroll
    for (int mi = 0; mi < 2; mi++)
        #pragma unroll
        for (int nj = 0; nj < 4; nj++)
            #pragma unroll
            for (int r = 0; r < 4; r++) acc[mi][nj][r] = 0.f;

    const int NC = K >> 5;

    #define GCPA(c, s) do {                                                     \
        const uint32_t stb_ = sb + (uint32_t)(s) * (GST * 2);                   \
        _Pragma("unroll")                                                       \
        for (int j_ = 0; j_ < 2; j_++) {                                        \
            int idx_ = tid + j_ * 256;                                          \
            int r_ = idx_ >> 2, q_ = idx_ & 3;                                  \
            size_t off_ = (size_t)(bm + r_) * K + (c) * 32 + q_ * 8;            \
            cp16(stb_ + (uint32_t)(r_ * 40 + q_ * 8) * 2, Ah + off_);           \
            cp16(stb_ + (uint32_t)(5120 + r_ * 40 + q_ * 8) * 2, Al + off_);    \
        }                                                                       \
        {                                                                       \
            int r_ = tid >> 3, q_ = tid & 7;                                    \
            size_t off_ = (size_t)((c) * 32 + r_) * N + bn + q_ * 8;            \
            cp16(stb_ + (uint32_t)(10240 + r_ * 72 + q_ * 8) * 2, Bh + off_);   \
            cp16(stb_ + (uint32_t)(12544 + r_ * 72 + q_ * 8) * 2, Bl + off_);   \
        }                                                                       \
    } while (0)

    GCPA(0, 0); cp_commit();
    if (NC > 1) GCPA(1, 1);
    cp_commit();

    for (int c = 0; c < NC; c++) {
        CP_WAIT1();
        __syncthreads();

        __half* st = hsm + (c & 1) * GST;
        #pragma unroll
        for (int ks = 0; ks < 2; ks++) {
            const int kb = ks * 16;
            uint32_t Ahf[2][4], Alf[2][4], Bhf[2][4], Blf[2][4];
            const int arow = (lane & 15), acol = kb + (lane >> 4) * 8;
            #pragma unroll
            for (int mi = 0; mi < 2; mi++) {
                __half* ap = st + (wm + mi * 16 + arow) * 40 + acol;
                LDSM4(Ahf[mi], ap);
                LDSM4(Alf[mi], ap + 5120);
            }
            const int krow = kb + ((lane >> 3) & 1) * 8 + (lane & 7);
            #pragma unroll
            for (int nq = 0; nq < 2; nq++) {
                const int ncol = wn + nq * 16 + ((lane >> 4) & 1) * 8;
                __half* bp = st + 10240 + krow * 72 + ncol;
                LDSM4T(Bhf[nq], bp);
                LDSM4T(Blf[nq], bp + 2304);
            }
            #pragma unroll
            for (int mi = 0; mi < 2; mi++)
                #pragma unroll
                for (int nj = 0; nj < 4; nj++) {
                    const uint32_t* bh = &Bhf[nj >> 1][(nj & 1) * 2];
                    const uint32_t* bl = &Blf[nj >> 1][(nj & 1) * 2];
                    hmma(acc[mi][nj], Ahf[mi], bh);
                    hmma(acc[mi][nj], Ahf[mi], bl);
                    hmma(acc[mi][nj], Alf[mi], bh);
                }
        }
        __syncthreads();
        if (c + 2 < NC) GCPA(c + 2, c & 1);
        cp_commit();
    }

    #pragma unroll
    for (int mi = 0; mi < 2; mi++) {
        #pragma unroll
        for (int nj = 0; nj < 4; nj++) {
            const int row = bm + wm + mi * 16 + g;
            const int col = bn + wn + nj * 8 + t * 2;
            float2 bv = *(const float2*)(bias + col);
            float2 w0, w1;
            w0.x = acc[mi][nj][0] + bv.x; w0.y = acc[mi][nj][1] + bv.y;
            w1.x = acc[mi][nj][2] + bv.x; w1.y = acc[mi][nj][3] + bv.y;
            if (act) {
                w0.x = fmaxf(w0.x, 0.f); w0.y = fmaxf(w0.y, 0.f);
                w1.x = fmaxf(w1.x, 0.f); w1.y = fmaxf(w1.y, 0.f);
            }
            if (c32) {
                *(float2*)(c32 + (size_t)row * N + col) = w0;
                *(float2*)(c32 + (size_t)(row + 8) * N + col) = w1;
            }
            if (ch) {
                uint32_t hh_, ll_;
                split2(w0.x, w0.y, hh_, ll_);
                *(uint32_t*)(ch + (size_t)row * N + col) = hh_;
                *(uint32_t*)(cl + (size_t)row * N + col) = ll_;
                split2(w1.x, w1.y, hh_, ll_);
                *(uint32_t*)(ch + (size_t)(row + 8) * N + col) = hh_;
                *(uint32_t*)(cl + (size_t)(row + 8) * N + col) = ll_;
            }
        }
    }
    #undef GCPA
}

// ---------------- fp16-pair flash attention, split-KV x2, cp.async ----------
// CTA: 128 q-rows x 1 head x 1 KV-half; 4 warps x 32 q-rows; KV chunks of 64.
// smem halves: Qh@0 Ql@9216; stages@18432: per-stage Kh|Kl|Vh|Vl (4608 each).
#define ASMEM 110592

__global__ __launch_bounds__(128, 2) void attn_mma(
    const __half* __restrict__ Qh_g, const __half* __restrict__ Ql_g,
    const __half* __restrict__ Kh_g, const __half* __restrict__ Kl_g,
    const __half* __restrict__ Vh_g, const __half* __restrict__ Vl_g,
    const float* __restrict__ mask,
    float* __restrict__ Opart, float* __restrict__ ml,
    int Tk, int maskFull)
{
    extern __shared__ __half hsm[];
    const uint32_t sb = (uint32_t)__cvta_generic_to_shared(hsm);
    const int tid = threadIdx.x;
    const int wid = tid >> 5, lane = tid & 31;
    const int g = lane >> 2, t = lane & 3;
    const int q0 = blockIdx.x * 128, hc = blockIdx.y * 64;
    const int s = blockIdx.z;
    const int kbase = s * (Tk >> 1);
    const int wm = wid * 32;
    float* op = Opart + (size_t)s * T2 * EE;

    #define ACPKV(c, st_) do {                                                  \
        const uint32_t stb_ = sb + (uint32_t)(18432 + (st_) * 18432) * 2;       \
        const int kr0_ = kbase + (c) * 64;                                      \
        _Pragma("unroll")                                                       \
        for (int j_ = 0; j_ < 4; j_++) {                                        \
            int idx_ = tid + j_ * 128;                                          \
            int r_ = idx_ >> 3, q_ = idx_ & 7;                                  \
            size_t off_ = (size_t)(kr0_ + r_) * EE + hc + q_ * 8;               \
            uint32_t d_ = (uint32_t)(r_ * 72 + q_ * 8) * 2;                     \
            cp16(stb_ + d_, Kh_g + off_);                                       \
            cp16(stb_ + 9216 + d_, Kl_g + off_);                                \
            cp16(stb_ + 18432 + d_, Vh_g + off_);                               \
            cp16(stb_ + 27648 + d_, Vl_g + off_);                               \
        }                                                                       \
    } while (0)

    // Q + KV0 as group 0
    #pragma unroll
    for (int j = 0; j < 8; j++) {
        int idx = tid + j * 128;
        int r = idx >> 3, q = idx & 7;
        size_t off = (size_t)(q0 + r) * EE + hc + q * 8;
        cp16(sb + (uint32_t)(r * 72 + q * 8) * 2, Qh_g + off);
        cp16(sb + 18432 + (uint32_t)(r * 72 + q * 8) * 2, Ql_g + off);
    }
    ACPKV(0, 0); cp_commit();
    const int NCH = Tk >> 7;
    if (NCH > 1) ACPKV(1, 1);
    cp_commit();

    float m_run[4], l_run[4];
    #pragma unroll
    for (int r = 0; r < 4; r++) { m_run[r] = -1e30f; l_run[r] = 0.f; }
    float oacc[2][8][4];
    #pragma unroll
    for (int mi = 0; mi < 2; mi++)
        #pragma unroll
        for (int nj = 0; nj < 8; nj++)
            #pragma unroll
            for (int r = 0; r < 4; r++) oacc[mi][nj][r] = 0.f;

    for (int c = 0; c < NCH; c++) {
        const int kr0 = kbase + c * 64;
        CP_WAIT1();
        __syncthreads();

        __half* Kst = hsm + 18432 + (c & 1) * 18432;   // lo at +4608
        __half* Vst = Kst + 9216;                      // lo at +4608

        // ---- S = Q @ K^T ----
        float sreg[2][8][4];
        #pragma unroll
        for (int mi = 0; mi < 2; mi++)
            #pragma unroll
            for (int nj = 0; nj < 8; nj++)
                #pragma unroll
                for (int r = 0; r < 4; r++) sreg[mi][nj][r] = 0.f;

        #pragma unroll
        for (int ks = 0; ks < 4; ks++) {
            uint32_t qh[2][4], ql[2][4];
            #pragma unroll
            for (int mi = 0; mi < 2; mi++) {
                __half* qp = hsm + (wm + mi * 16 + (lane & 15)) * 72 + ks * 16 + (lane >> 4) * 8;
                LDSM4(qh[mi], qp);
                LDSM4(ql[mi], qp + 9216);
            }
            const int kvrow = ((lane >> 4) & 1) * 8 + (lane & 7);
            const int dcol = ks * 16 + ((lane >> 3) & 1) * 8;
            #pragma unroll
            for (int nq = 0; nq < 4; nq++) {
                uint32_t kh4[4], kl4[4];
                __half* kp = Kst + (nq * 16 + kvrow) * 72 + dcol;
                LDSM4(kh4, kp);
                LDSM4(kl4, kp + 4608);
                #pragma unroll
                for (int mi = 0; mi < 2; mi++)
                    #pragma unroll
                    for (int hb = 0; hb < 2; hb++) {
                        float* sd = sreg[mi][nq * 2 + hb];
                        const uint32_t* bh = kh4 + hb * 2;
                        const uint32_t* bl = kl4 + hb * 2;
                        hmma(sd, qh[mi], bh);
                        hmma(sd, qh[mi], bl);
                        hmma(sd, ql[mi], bh);
                    }
            }
        }

        // ---- mask add ----
        if (maskFull) {
            #pragma unroll
            for (int mi = 0; mi < 2; mi++) {
                const int row0 = q0 + wm + mi * 16 + g;
                #pragma unroll
                for (int nj = 0; nj < 8; nj++) {
                    float2 m0 = *(const float2*)(mask + (size_t)row0 * Tk + kr0 + nj * 8 + t * 2);
                    float2 m1 = *(const float2*)(mask + (size_t)(row0 + 8) * Tk + kr0 + nj * 8 + t * 2);
                    sreg[mi][nj][0] += m0.x; sreg[mi][nj][1] += m0.y;
                    sreg[mi][nj][2] += m1.x; sreg[mi][nj][3] += m1.y;
                }
            }
        } else {
            #pragma unroll
            for (int nj = 0; nj < 8; nj++) {
                float2 mv = *(const float2*)(mask + kr0 + nj * 8 + t * 2);
                #pragma unroll
                for (int mi = 0; mi < 2; mi++) {
                    sreg[mi][nj][0] += mv.x; sreg[mi][nj][1] += mv.y;
                    sreg[mi][nj][2] += mv.x; sreg[mi][nj][3] += mv.y;
                }
            }
        }

        // ---- online softmax ----
        #pragma unroll
        for (int mi = 0; mi < 2; mi++)
            #pragma unroll
            for (int rr = 0; rr < 2; rr++) {
                const int r = mi * 2 + rr;
                float tm = -1e30f;
                #pragma unroll
                for (int nj = 0; nj < 8; nj++)
                    tm = fmaxf(tm, fmaxf(sreg[mi][nj][rr * 2], sreg[mi][nj][rr * 2 + 1]));
                tm = fmaxf(tm, __shfl_xor_sync(0xffffffffu, tm, 1));
                tm = fmaxf(tm, __shfl_xor_sync(0xffffffffu, tm, 2));
                float nm = fmaxf(m_run[r], tm);
                float sc = __expf(m_run[r] - nm);
                float rs = 0.f;
                #pragma unroll
                for (int nj = 0; nj < 8; nj++) {
                    float p0 = __expf(sreg[mi][nj][rr * 2] - nm);
                    float p1 = __expf(sreg[mi][nj][rr * 2 + 1] - nm);
                    sreg[mi][nj][rr * 2] = p0; sreg[mi][nj][rr * 2 + 1] = p1;
                    rs += p0 + p1;
                }
                rs += __shfl_xor_sync(0xffffffffu, rs, 1);
                rs += __shfl_xor_sync(0xffffffffu, rs, 2);
                l_run[r] = l_run[r] * sc + rs;
                m_run[r] = nm;
                #pragma unroll
                for (int nj = 0; nj < 8; nj++) {
                    oacc[mi][nj][rr * 2] *= sc;
                    oacc[mi][nj][rr * 2 + 1] *= sc;
                }
            }

        // ---- O += P @ V ----
        #pragma unroll
        for (int ks = 0; ks < 4; ks++) {
            uint32_t ph[2][4], pl[2][4];
            #pragma unroll
            for (int mi = 0; mi < 2; mi++) {
                split2(sreg[mi][2 * ks][0],     sreg[mi][2 * ks][1],     ph[mi][0], pl[mi][0]);
                split2(sreg[mi][2 * ks][2],     sreg[mi][2 * ks][3],     ph[mi][1], pl[mi][1]);
                split2(sreg[mi][2 * ks + 1][0], sreg[mi][2 * ks + 1][1], ph[mi][2], pl[mi][2]);
                split2(sreg[mi][2 * ks + 1][2], sreg[mi][2 * ks + 1][3], ph[mi][3], pl[mi][3]);
            }
            const int krow = ks * 16 + ((lane >> 3) & 1) * 8 + (lane & 7);
            const int nc0 = ((lane >> 4) & 1) * 8;
            #pragma unroll
            for (int nq = 0; nq < 4; nq++) {
                uint32_t vh4[4], vl4[4];
                __half* vp = Vst + krow * 72 + nq * 16 + nc0;
                LDSM4T(vh4, vp);
                LDSM4T(vl4, vp + 4608);
                #pragma unroll
                for (int mi = 0; mi < 2; mi++)
                    #pragma unroll
                    for (int hb = 0; hb < 2; hb++) {
                        float* od = oacc[mi][nq * 2 + hb];
                        const uint32_t* bh = vh4 + hb * 2;
                        const uint32_t* bl = vl4 + hb * 2;
                        hmma(od, ph[mi], bh);
                        hmma(od, ph[mi], bl);
                        hmma(od, pl[mi], bh);
                    }
            }
        }
        __syncthreads();
        if (c + 2 < NCH) ACPKV(c + 2, c & 1);
        cp_commit();
    }

    // epilogue: unnormalized partials + (m, l)
    #pragma unroll
    for (int mi = 0; mi < 2; mi++) {
        const int row = q0 + wm + mi * 16 + g;
        #pragma unroll
        for (int nj = 0; nj < 8; nj++) {
            const int col = hc + nj * 8 + t * 2;
            *(float2*)(op + (size_t)row * EE + col) =
                make_float2(oacc[mi][nj][0], oacc[mi][nj][1]);
            *(float2*)(op + (size_t)(row + 8) * EE + col) =
                make_float2(oacc[mi][nj][2], oacc[mi][nj][3]);
        }
        if (t == 0) {
            const size_t base = ((size_t)s * NH + blockIdx.y) * T2;
            ml[(base + row) * 2 + 0] = m_run[mi * 2];
            ml[(base + row) * 2 + 1] = l_run[mi * 2];
            ml[(base + row + 8) * 2 + 0] = m_run[mi * 2 + 1];
            ml[(base + row + 8) * 2 + 1] = l_run[mi * 2 + 1];
        }
    }
    #undef ACPKV
}

// ---------------- combine split-KV partials -> att split pairs --------------
__global__ __launch_bounds__(128) void attn_combine(
    const float* __restrict__ Opart, const float* __restrict__ ml,
    __half* __restrict__ oh, __half* __restrict__ ol)
{
    const int row = blockIdx.x;
    const int tid = threadIdx.x;
    const int col = tid * 4;
    const int h = tid >> 4;

    float m0 = ml[(((size_t)0 * NH + h) * T2 + row) * 2 + 0];
    float l0 = ml[(((size_t)0 * NH + h) * T2 + row) * 2 + 1];
    float m1 = ml[(((size_t)1 * NH + h) * T2 + row) * 2 + 0];
    float l1 = ml[(((size_t)1 * NH + h) * T2 + row) * 2 + 1];
    float m = fmaxf(m0, m1);
    float w0 = __expf(m0 - m), w1 = __expf(m1 - m);
    float inv = 1.f / (l0 * w0 + l1 * w1);

    float4 a = *(const float4*)(Opart + (size_t)row * EE + col);
    float4 b = *(const float4*)(Opart + (size_t)T2 * EE + (size_t)row * EE + col);
    float4 w;
    w.x = (a.x * w0 + b.x * w1) * inv;
    w.y = (a.y * w0 + b.y * w1) * inv;
    w.z = (a.z * w0 + b.z * w1) * inv;
    w.w = (a.w * w0 + b.w * w1) * inv;
    uint32_t h01, l01v, h23, l23;
    split2(w.x, w.y, h01, l01v); split2(w.z, w.w, h23, l23);
    *(uint2*)(oh + (size_t)row * EE + col) = make_uint2(h01, h23);
    *(uint2*)(ol + (size_t)row * EE + col) = make_uint2(l01v, l23);
}

// ---------------- out = LN(relu(h + a)), writes fp32 + split pairs ----------
__global__ __launch_bounds__(128) void add_relu_ln(
    const float* __restrict__ h, const float* __restrict__ a,
    const float* __restrict__ g, const float* __restrict__ b,
    float* __restrict__ out, __half* __restrict__ oh, __half* __restrict__ ol)
{
    __shared__ float red[4];
    const int row = blockIdx.x;
    const int tid = threadIdx.x;
    const int c = tid * 4;

    float4 hv = *(const float4*)(h + (size_t)row * EE + c);
    float4 av = *(const float4*)(a + (size_t)row * EE + c);
    float v[4] = { fmaxf(hv.x + av.x, 0.f), fmaxf(hv.y + av.y, 0.f),
                   fmaxf(hv.z + av.z, 0.f), fmaxf(hv.w + av.w, 0.f) };

    float s = v[0] + v[1] + v[2] + v[3];
    #pragma unroll
    for (int m = 16; m; m >>= 1) s += __shfl_xor_sync(0xffffffffu, s, m);
    if ((tid & 31) == 0) red[tid >> 5] = s;
    __syncthreads();
    float mean = (red[0] + red[1] + red[2] + red[3]) * (1.f / EE);
    __syncthreads();

    float d = 0.f;
    #pragma unroll
    for (int j = 0; j < 4; j++) { float tt = v[j] - mean; d += tt * tt; }
    #pragma unroll
    for (int m = 16; m; m >>= 1) d += __shfl_xor_sync(0xffffffffu, d, m);
    if ((tid & 31) == 0) red[tid >> 5] = d;
    __syncthreads();
    float var = (red[0] + red[1] + red[2] + red[3]) * (1.f / EE);
    float rstd = rsqrtf(var + 1e-5f);

    float4 gv = *(const float4*)(g + c);
    float4 bv = *(const float4*)(b + c);
    float4 w = make_float4((v[0] - mean) * rstd * gv.x + bv.x,
                           (v[1] - mean) * rstd * gv.y + bv.y,
                           (v[2] - mean) * rstd * gv.z + bv.z,
                           (v[3] - mean) * rstd * gv.w + bv.w);
    *(float4*)(out + (size_t)row * EE + c) = w;
    uint32_t h01, l01, h23, l23;
    split2(w.x, w.y, h01, l01); split2(w.z, w.w, h23, l23);
    *(uint2*)(oh + (size_t)row * EE + c) = make_uint2(h01, h23);
    *(uint2*)(ol + (size_t)row * EE + c) = make_uint2(l01, l23);
}

// ---------------- launch ----------------
extern "C" void kernel_launch(void* const* d_in, const int* in_sizes, int n_in,
                              void* d_out, int out_size)
{
    (void)in_sizes; (void)n_in; (void)out_size;
    const float* x      = (const float*)d_in[0];
    const float* enc    = (const float*)d_in[1];
    const float* am     = (const float*)d_in[2];
    const float* em     = (const float*)d_in[3];
    const float* k_w    = (const float*)d_in[4];
    const float* k_b    = (const float*)d_in[5];
    const float* v_w    = (const float*)d_in[6];
    const float* v_b    = (const float*)d_in[7];
    const float* sa_q_w = (const float*)d_in[8];  const float* sa_q_b = (const float*)d_in[9];
    const float* sa_k_w = (const float*)d_in[10]; const float* sa_k_b = (const float*)d_in[11];
    const float* sa_v_w = (const float*)d_in[12]; const float* sa_v_b = (const float*)d_in[13];
    const float* sa_o_w = (const float*)d_in[14]; const float* sa_o_b = (const float*)d_in[15];
    const float* n1_g   = (const float*)d_in[16]; const float* n1_b   = (const float*)d_in[17];
    const float* ca_o_w = (const float*)d_in[18]; const float* ca_o_b = (const float*)d_in[19];
    const float* n2_g   = (const float*)d_in[20]; const float* n2_b   = (const float*)d_in[21];
    const float* f1_w   = (const float*)d_in[22]; const float* f1_b   = (const float*)d_in[23];
    const float* f2_w   = (const float*)d_in[24]; const float* f2_b   = (const float*)d_in[25];
    const float* n3_g   = (const float*)d_in[26]; const float* n3_b   = (const float*)d_in[27];

    float *h, *proj, *op, *ml;
    cudaGetSymbolAddress((void**)&h,    g_h);
    cudaGetSymbolAddress((void**)&proj, g_proj);
    cudaGetSymbolAddress((void**)&op,   g_op);
    cudaGetSymbolAddress((void**)&ml,   g_ml);
    __half *hh, *hl, *qh, *ql, *kh, *kl, *vh, *vl, *atth, *attl;
    __half *ffnh, *ffnl, *Ksh, *Ksl, *Vsh, *Vsl, *ench, *encl, *wsh, *wsl;
    cudaGetSymbolAddress((void**)&hh, g_hh);     cudaGetSymbolAddress((void**)&hl, g_hl);
    cudaGetSymbolAddress((void**)&qh, g_qh);     cudaGetSymbolAddress((void**)&ql, g_ql);
    cudaGetSymbolAddress((void**)&kh, g_kh);     cudaGetSymbolAddress((void**)&kl, g_kl);
    cudaGetSymbolAddress((void**)&vh, g_vh);     cudaGetSymbolAddress((void**)&vl, g_vl);
    cudaGetSymbolAddress((void**)&atth, g_atth); cudaGetSymbolAddress((void**)&attl, g_attl);
    cudaGetSymbolAddress((void**)&ffnh, g_ffnh); cudaGetSymbolAddress((void**)&ffnl, g_ffnl);
    cudaGetSymbolAddress((void**)&Ksh, g_Ksh);   cudaGetSymbolAddress((void**)&Ksl, g_Ksl);
    cudaGetSymbolAddress((void**)&Vsh, g_Vsh);   cudaGetSymbolAddress((void**)&Vsl, g_Vsl);
    cudaGetSymbolAddress((void**)&ench, g_ench); cudaGetSymbolAddress((void**)&encl, g_encl);
    cudaGetSymbolAddress((void**)&wsh, g_wsh);   cudaGetSymbolAddress((void**)&wsl, g_wsl);

    cudaFuncSetAttribute((const void*)attn_mma,
                         cudaFuncAttributeMaxDynamicSharedMemorySize, ASMEM);
    cudaFuncSetAttribute((const void*)gemm_mma,
                         cudaFuncAttributeMaxDynamicSharedMemorySize, GSMEM);

    const dim3 gP (EE / 64, T2 / 128, 1);
    const dim3 gP3(EE / 64, T2 / 128, 3);
    const dim3 gP2(EE / 64, T2 / 128, 2);
    const dim3 gF (FF / 64, T2 / 128, 1);
    const dim3 gA (T2 / 128, NH, 2);

    // weight offsets (halves)
    const long WO_KW = 0, WO_VW = WB0;
    #define WO_SAQ(l) (WB1 + (long)(l) * 262144)
    #define WO_SAK(l) (WB2 + (long)(l) * 262144)
    #define WO_SAV(l) (WB3 + (long)(l) * 262144)
    #define WO_SAO(l) (WB4 + (long)(l) * 262144)
    #define WO_CAO(l) (WB5 + (long)(l) * 262144)
    #define WO_F1(l)  (WB6 + (long)(l) * 1048576)
    #define WO_F2(l)  (WB7 + (long)(l) * 1048576)

    wsplit_kernel<<<(TOTALW / 4 + 255) / 256, 256>>>(
        k_w, v_w, sa_q_w, sa_k_w, sa_v_w, sa_o_w, ca_o_w, f1_w, f2_w, wsh, wsl);
    copy_split<<<T2 * EE / 1024, 256>>>(x, h, hh, hl);
    copy_split<<<T1 * EE / 1024, 256>>>(enc, nullptr, ench, encl);
    gemm_mma<<<gP2, 256, GSMEM>>>(ench, encl, wsh, wsl,
        WO_KW, k_b, nullptr, Ksh, Ksl,
        WO_VW, v_b, nullptr, Vsh, Vsl,
        WO_VW, v_b, nullptr, Vsh, Vsl, EE, EE, 0);

    for (int l = 0; l < NL; l++) {
        const size_t bo = (size_t)l * EE;
        // self-attention: fused QKV projections
        gemm_mma<<<gP3, 256, GSMEM>>>(hh, hl, wsh, wsl,
            WO_SAQ(l), sa_q_b + bo, nullptr, qh, ql,
            WO_SAK(l), sa_k_b + bo, nullptr, kh, kl,
            WO_SAV(l), sa_v_b + bo, nullptr, vh, vl, EE, EE, 0);
        attn_mma<<<gA, 128, ASMEM>>>(qh, ql, kh, kl, vh, vl, am, op, ml, T2, 1);
        attn_combine<<<T2, 128>>>(op, ml, atth, attl);
        gemm_mma<<<gP, 256, GSMEM>>>(atth, attl, wsh, wsl,
            WO_SAO(l), sa_o_b + bo, proj, nullptr, nullptr,
            WO_SAO(l), sa_o_b + bo, proj, nullptr, nullptr,
            WO_SAO(l), sa_o_b + bo, proj, nullptr, nullptr, EE, EE, 1);
        add_relu_ln<<<T2, 128>>>(h, proj, n1_g + bo, n1_b + bo, h, hh, hl);
        // cross-attention (Q = h pairs)
        attn_mma<<<gA, 128, ASMEM>>>(hh, hl, Ksh, Ksl, Vsh, Vsl, em, op, ml, T1, 0);
        attn_combine<<<T2, 128>>>(op, ml, atth, attl);
        gemm_mma<<<gP, 256, GSMEM>>>(atth, attl, wsh, wsl,
            WO_CAO(l), ca_o_b + bo, proj, nullptr, nullptr,
            WO_CAO(l), ca_o_b + bo, proj, nullptr, nullptr,
            WO_CAO(l), ca_o_b + bo, proj, nullptr, nullptr, EE, EE, 1);
        add_relu_ln<<<T2, 128>>>(h, proj, n2_g + bo, n2_b + bo, h, hh, hl);
        // FFN
        gemm_mma<<<gF, 256, GSMEM>>>(hh, hl, wsh, wsl,
            WO_F1(l), f1_b + (size_t)l * FF, nullptr, ffnh, ffnl,
            WO_F1(l), f1_b + (size_t)l * FF, nullptr, ffnh, ffnl,
            WO_F1(l), f1_b + (size_t)l * FF, nullptr, ffnh, ffnl, FF, EE, 1);
        gemm_mma<<<gP, 256, GSMEM>>>(ffnh, ffnl, wsh, wsl,
            WO_F2(l), f2_b + bo, proj, nullptr, nullptr,
            WO_F2(l), f2_b + bo, proj, nullptr, nullptr,
            WO_F2(l), f2_b + bo, proj, nullptr, nullptr, EE, FF, 0);
        add_relu_ln<<<T2, 128>>>(h, proj, n3_g + bo, n3_b + bo, h, hh, hl);
    }

    copyk<<<T2 * EE / 1024, 256>>>(h, (float*)d_out);
}

// round 8
// speedup vs baseline: 1.0133x; 1.0133x over previous
#include <cuda_runtime.h>
#include <cuda_fp16.h>
#include <cstdint>

#define T2 2048
#define T1 2048
#define EE 512
#define FF 2048
#define NL 4
#define NH 8

// ---------------- scratch (device globals; allocation-free) ----------------
__device__ float g_h    [T2*EE];
__device__ float g_q    [T2*EE];
__device__ float g_k    [T2*EE];
__device__ float g_v    [T2*EE];
__device__ float g_proj [T2*EE];
__device__ float g_proj2[T2*EE];
__device__ float g_ffn  [T2*FF];
__device__ float g_Ks   [T1*EE];
__device__ float g_Vs   [T1*EE];
__device__ float g_op   [2*T2*EE];      // split-KV partial O (unnormalized)
__device__ float g_ml   [2*NH*T2*2];    // split-KV per-row (m, l)
__device__ float g_mlw  [2*NH*T2];      // combine weights w0', w1'
__device__ float g_zb   [FF];           // zero bias (zero-initialized)

// ---------------- helpers ----------------
__device__ __forceinline__ void hmma(float* d, const uint32_t* a, const uint32_t* b) {
    asm volatile(
        "mma.sync.aligned.m16n8k16.row.col.f32.f16.f16.f32 "
        "{%0,%1,%2,%3}, {%4,%5,%6,%7}, {%8,%9}, {%0,%1,%2,%3};"
        : "+f"(d[0]), "+f"(d[1]), "+f"(d[2]), "+f"(d[3])
        : "r"(a[0]), "r"(a[1]), "r"(a[2]), "r"(a[3]), "r"(b[0]), "r"(b[1]));
}
#define LDSM4(R, PTR) do {                                                     \
    uint32_t a_ = (uint32_t)__cvta_generic_to_shared(PTR);                     \
    asm volatile("ldmatrix.sync.aligned.m8n8.x4.shared.b16 {%0,%1,%2,%3}, [%4];" \
        : "=r"((R)[0]), "=r"((R)[1]), "=r"((R)[2]), "=r"((R)[3]) : "r"(a_));   \
} while (0)
#define LDSM4T(R, PTR) do {                                                    \
    uint32_t a_ = (uint32_t)__cvta_generic_to_shared(PTR);                     \
    asm volatile("ldmatrix.sync.aligned.m8n8.x4.trans.shared.b16 {%0,%1,%2,%3}, [%4];" \
        : "=r"((R)[0]), "=r"((R)[1]), "=r"((R)[2]), "=r"((R)[3]) : "r"(a_));   \
} while (0)

__device__ __forceinline__ uint32_t packh2(float x, float y) {
    __half2 h = __floats2half2_rn(x, y);
    return *reinterpret_cast<uint32_t*>(&h);
}
// 2-term fp16 split: (x,y) -> hi pair + lo pair; x ≈ hi + lo to ~2.4e-7 rel.
__device__ __forceinline__ void split2(float x, float y, uint32_t& hi, uint32_t& lo) {
    float hx = __half2float(__float2half_rn(x));
    float hy = __half2float(__float2half_rn(y));
    hi = packh2(hx, hy);
    lo = packh2(x - hx, y - hy);
}

// ---------------- elementwise copy ----------------
__global__ void copyk(const float* __restrict__ in, float* __restrict__ out) {
    size_t i = ((size_t)blockIdx.x * blockDim.x + threadIdx.x) * 4;
    *(float4*)(out + i) = *(const float4*)(in + i);
}

// ---------------- ml -> combine weights ----------------
__global__ __launch_bounds__(256) void mlw_kernel(
    const float* __restrict__ ml, float* __restrict__ mlw)
{
    const int i = blockIdx.x * 256 + threadIdx.x;   // i = head*T2 + row
    float m0 = ml[i * 2 + 0];
    float l0 = ml[i * 2 + 1];
    float m1 = ml[(NH * T2 + i) * 2 + 0];
    float l1 = ml[(NH * T2 + i) * 2 + 1];
    float m = fmaxf(m0, m1);
    float w0 = __expf(m0 - m), w1 = __expf(m1 - m);
    float inv = 1.f / (l0 * w0 + l1 * w1);
    mlw[i] = w0 * inv;
    mlw[NH * T2 + i] = w1 * inv;
}

// ---------------- fp16-split GEMM: C = act(A @ B + bias), tile 128x64 -------
// 256 threads, 8 warps (4x2), warp 32x32, BK=32, 2-stage register pipeline.
// CMB=1: A is split-KV partial base (op); combine with mlw during load.
// blockIdx.z selects (B,bias,C) triple (fused QKV / split-K).
// stage halves: Ah[128][40]@0 Al@5120 Bh[32][72]@10240 Bl@12544; GST=14848.
#define GST 14848
#define GSMEM (2 * GST * 2)   // 59392 B

template<int CMB>
__global__ __launch_bounds__(256, 2) void gemm_mma(
    const float* __restrict__ A, const float* __restrict__ mlw,
    const float* __restrict__ B0, const float* __restrict__ b0, float* __restrict__ C0,
    const float* __restrict__ B1, const float* __restrict__ b1, float* __restrict__ C1,
    const float* __restrict__ B2, const float* __restrict__ b2, float* __restrict__ C2,
    int N, int lda, int kCnt, int aoffZ, int act)
{
    extern __shared__ __half hsm[];
    const int z = blockIdx.z;
    const float* B    = (z == 0) ? B0 : ((z == 1) ? B1 : B2);
    const float* bias = (z == 0) ? b0 : ((z == 1) ? b1 : b2);
    float*       C    = (z == 0) ? C0 : ((z == 1) ? C1 : C2);
    const float* Az   = A + (size_t)z * aoffZ;

    const int tid = threadIdx.x;
    const int wid = tid >> 5, lane = tid & 31;
    const int g = lane >> 2, t = lane & 3;
    const int bm = blockIdx.y * 128, bn = blockIdx.x * 64;
    const int wm = (wid >> 1) * 32, wn = (wid & 1) * 32;

    float acc[2][4][4];
    #pragma unroll
    for (int mi = 0; mi < 2; mi++)
        #pragma unroll
        for (int nj = 0; nj < 4; nj++)
            #pragma unroll
            for (int r = 0; r < 4; r++) acc[mi][nj][r] = 0.f;

    const int NC = kCnt >> 5;
    float4 ra[4], rb[2];

    #define GLDG(c) do {                                                        \
        _Pragma("unroll")                                                       \
        for (int j_ = 0; j_ < 4; j_++) {                                        \
            int idx_ = tid + j_ * 256;                                          \
            int row_ = bm + (idx_ >> 3);                                        \
            int col_ = (c) * 32 + (idx_ & 7) * 4;                               \
            if (CMB) {                                                          \
                int head_ = (c) >> 1;                                           \
                float w0_ = mlw[head_ * T2 + row_];                             \
                float w1_ = mlw[NH * T2 + head_ * T2 + row_];                   \
                float4 a0_ = *(const float4*)(Az + (size_t)row_ * EE + col_);   \
                float4 a1_ = *(const float4*)(Az + (size_t)T2 * EE              \
                                              + (size_t)row_ * EE + col_);      \
                ra[j_].x = a0_.x * w0_ + a1_.x * w1_;                           \
                ra[j_].y = a0_.y * w0_ + a1_.y * w1_;                           \
                ra[j_].z = a0_.z * w0_ + a1_.z * w1_;                           \
                ra[j_].w = a0_.w * w0_ + a1_.w * w1_;                           \
            } else {                                                            \
                ra[j_] = *(const float4*)(Az + (size_t)row_ * lda + col_);      \
            }                                                                   \
        }                                                                       \
        _Pragma("unroll")                                                       \
        for (int j_ = 0; j_ < 2; j_++) {                                        \
            int idx_ = tid + j_ * 256;                                          \
            rb[j_] = *(const float4*)(B + (size_t)((c) * 32 + (idx_ >> 4)) * N  \
                                      + bn + (idx_ & 15) * 4);                  \
        }                                                                       \
    } while (0)

    #define GSTS(s) do {                                                        \
        __half* st_ = hsm + (s) * GST;                                          \
        _Pragma("unroll")                                                       \
        for (int j_ = 0; j_ < 4; j_++) {                                        \
            int idx_ = tid + j_ * 256;                                          \
            int m_ = idx_ >> 3, kq_ = idx_ & 7;                                 \
            uint32_t h01, l01, h23, l23;                                        \
            split2(ra[j_].x, ra[j_].y, h01, l01);                               \
            split2(ra[j_].z, ra[j_].w, h23, l23);                               \
            *(uint2*)(st_ + m_ * 40 + kq_ * 4) = make_uint2(h01, h23);          \
            *(uint2*)(st_ + 5120 + m_ * 40 + kq_ * 4) = make_uint2(l01, l23);   \
        }                                                                       \
        _Pragma("unroll")                                                       \
        for (int j_ = 0; j_ < 2; j_++) {                                        \
            int idx_ = tid + j_ * 256;                                          \
            int k_ = idx_ >> 4, nq_ = idx_ & 15;                                \
            uint32_t h01, l01, h23, l23;                                        \
            split2(rb[j_].x, rb[j_].y, h01, l01);                               \
            split2(rb[j_].z, rb[j_].w, h23, l23);                               \
            *(uint2*)(st_ + 10240 + k_ * 72 + nq_ * 4) = make_uint2(h01, h23);  \
            *(uint2*)(st_ + 12544 + k_ * 72 + nq_ * 4) = make_uint2(l01, l23);  \
        }                                                                       \
    } while (0)

    GLDG(0); GSTS(0);
    if (NC > 1) GLDG(1);
    __syncthreads();

    for (int c = 0; c < NC; c++) {
        if (c + 1 < NC) GSTS((c + 1) & 1);
        if (c + 2 < NC) GLDG(c + 2);

        __half* st = hsm + (c & 1) * GST;
        #pragma unroll
        for (int ks = 0; ks < 2; ks++) {
            const int kb = ks * 16;
            uint32_t Ahf[2][4], Alf[2][4], Bhf[2][4], Blf[2][4];
            const int arow = (lane & 15), acol = kb + (lane >> 4) * 8;
            #pragma unroll
            for (int mi = 0; mi < 2; mi++) {
                __half* ap = st + (wm + mi * 16 + arow) * 40 + acol;
                LDSM4(Ahf[mi], ap);
                LDSM4(Alf[mi], ap + 5120);
            }
            const int krow = kb + ((lane >> 3) & 1) * 8 + (lane & 7);
            #pragma unroll
            for (int nq = 0; nq < 2; nq++) {
                const int ncol = wn + nq * 16 + ((lane >> 4) & 1) * 8;
                __half* bp = st + 10240 + krow * 72 + ncol;
                LDSM4T(Bhf[nq], bp);
                LDSM4T(Blf[nq], bp + 2304);
            }
            #pragma unroll
            for (int mi = 0; mi < 2; mi++)
                #pragma unroll
                for (int nj = 0; nj < 4; nj++) {
                    const uint32_t* bh = &Bhf[nj >> 1][(nj & 1) * 2];
                    const uint32_t* bl = &Blf[nj >> 1][(nj & 1) * 2];
                    hmma(acc[mi][nj], Ahf[mi], bh);
                    hmma(acc[mi][nj], Ahf[mi], bl);
                    hmma(acc[mi][nj], Alf[mi], bh);
                }
        }
        __syncthreads();
    }

    #pragma unroll
    for (int mi = 0; mi < 2; mi++) {
        #pragma unroll
        for (int nj = 0; nj < 4; nj++) {
            const int row = bm + wm + mi * 16 + g;
            const int col = bn + wn + nj * 8 + t * 2;
            float2 bv = *(const float2*)(bias + col);
            float2 w0, w1;
            w0.x = acc[mi][nj][0] + bv.x; w0.y = acc[mi][nj][1] + bv.y;
            w1.x = acc[mi][nj][2] + bv.x; w1.y = acc[mi][nj][3] + bv.y;
            if (act) {
                w0.x = fmaxf(w0.x, 0.f); w0.y = fmaxf(w0.y, 0.f);
                w1.x = fmaxf(w1.x, 0.f); w1.y = fmaxf(w1.y, 0.f);
            }
            *(float2*)(C + (size_t)row * N + col) = w0;
            *(float2*)(C + (size_t)(row + 8) * N + col) = w1;
        }
    }
    #undef GLDG
    #undef GSTS
}

// ---------------- fp16-split flash attention, split-KV x2 -------------------
// CTA: 128 q-rows x 1 head x 1 KV-half; 4 warps x 32 q-rows (2 mi tiles).
// KV chunks of 64. Writes UNNORMALIZED O partials + (m,l).
// smem halves: Qh[128][72]@0 Ql@9216 Kh[64][72]@18432 Kl@23040 Vh@27648 Vl@32256
#define ASMEM 73728

__global__ __launch_bounds__(128, 2) void attn_mma(
    const float* __restrict__ Q, const float* __restrict__ K,
    const float* __restrict__ V, const float* __restrict__ mask,
    float* __restrict__ Opart, float* __restrict__ ml,
    int Tk, int maskFull)
{
    extern __shared__ __half hsm[];
    __half* Qh = hsm;              // lo at +9216
    __half* Kh = hsm + 18432;      // lo at +4608
    __half* Vh = hsm + 27648;      // lo at +4608

    const int tid = threadIdx.x;
    const int wid = tid >> 5, lane = tid & 31;
    const int g = lane >> 2, t = lane & 3;
    const int q0 = blockIdx.x * 128, hc = blockIdx.y * 64;
    const int s = blockIdx.z;
    const int kbase = s * (Tk >> 1);
    const int wm = wid * 32;
    float* op = Opart + (size_t)s * T2 * EE;

    // Q tile 128x64 -> split fp16
    #pragma unroll
    for (int j = 0; j < 16; j++) {
        int idx = tid + j * 128;
        int r = idx >> 4, dq = idx & 15;
        float4 qv = *(const float4*)(Q + (size_t)(q0 + r) * EE + hc + dq * 4);
        uint32_t h01, l01, h23, l23;
        split2(qv.x, qv.y, h01, l01); split2(qv.z, qv.w, h23, l23);
        *(uint2*)(Qh + r * 72 + dq * 4) = make_uint2(h01, h23);
        *(uint2*)(Qh + 9216 + r * 72 + dq * 4) = make_uint2(l01, l23);
    }

    // shared K/V staging registers (disjoint lifetimes)
    float4 rkv[8];
    #pragma unroll
    for (int j = 0; j < 8; j++) {
        int idx = tid + j * 128;
        rkv[j] = *(const float4*)(K + (size_t)(kbase + (idx >> 4)) * EE + hc + (idx & 15) * 4);
    }

    float m_run[4], l_run[4];
    #pragma unroll
    for (int r = 0; r < 4; r++) { m_run[r] = -1e30f; l_run[r] = 0.f; }
    float oacc[2][8][4];
    #pragma unroll
    for (int mi = 0; mi < 2; mi++)
        #pragma unroll
        for (int nj = 0; nj < 8; nj++)
            #pragma unroll
            for (int r = 0; r < 4; r++) oacc[mi][nj][r] = 0.f;

    const int NCH = Tk >> 7;    // chunks of 64 within this half
    for (int c = 0; c < NCH; c++) {
        const int kr0 = kbase + c * 64;

        // ---- STS K (split) from rkv ----
        #pragma unroll
        for (int j = 0; j < 8; j++) {
            int idx = tid + j * 128;
            int kr = idx >> 4, dq = idx & 15;
            uint32_t h01, l01, h23, l23;
            split2(rkv[j].x, rkv[j].y, h01, l01); split2(rkv[j].z, rkv[j].w, h23, l23);
            *(uint2*)(Kh + kr * 72 + dq * 4) = make_uint2(h01, h23);
            *(uint2*)(Kh + 4608 + kr * 72 + dq * 4) = make_uint2(l01, l23);
        }
        __syncthreads();   // K (and Q on c=0) ready; all warps past PV(c-1)

        // ---- LDG V chunk c (latency hidden by S-MMA) ----
        #pragma unroll
        for (int j = 0; j < 8; j++) {
            int idx = tid + j * 128;
            rkv[j] = *(const float4*)(V + (size_t)(kr0 + (idx >> 4)) * EE + hc + (idx & 15) * 4);
        }

        // ---- S = Q @ K^T ----
        float sreg[2][8][4];
        #pragma unroll
        for (int mi = 0; mi < 2; mi++)
            #pragma unroll
            for (int nj = 0; nj < 8; nj++)
                #pragma unroll
                for (int r = 0; r < 4; r++) sreg[mi][nj][r] = 0.f;

        #pragma unroll
        for (int ks = 0; ks < 4; ks++) {
            uint32_t qh[2][4], ql[2][4];
            #pragma unroll
            for (int mi = 0; mi < 2; mi++) {
                __half* qp = Qh + (wm + mi * 16 + (lane & 15)) * 72 + ks * 16 + (lane >> 4) * 8;
                LDSM4(qh[mi], qp);
                LDSM4(ql[mi], qp + 9216);
            }
            const int kvrow = ((lane >> 4) & 1) * 8 + (lane & 7);
            const int dcol = ks * 16 + ((lane >> 3) & 1) * 8;
            #pragma unroll
            for (int nq = 0; nq < 4; nq++) {
                uint32_t kh4[4], kl4[4];
                __half* kp = Kh + (nq * 16 + kvrow) * 72 + dcol;
                LDSM4(kh4, kp);
                LDSM4(kl4, kp + 4608);
                #pragma unroll
                for (int mi = 0; mi < 2; mi++)
                    #pragma unroll
                    for (int hb = 0; hb < 2; hb++) {
                        float* sd = sreg[mi][nq * 2 + hb];
                        const uint32_t* bh = kh4 + hb * 2;
                        const uint32_t* bl = kl4 + hb * 2;
                        hmma(sd, qh[mi], bh);
                        hmma(sd, qh[mi], bl);
                        hmma(sd, ql[mi], bh);
                    }
            }
        }

        // ---- mask add ----
        if (maskFull) {
            #pragma unroll
            for (int mi = 0; mi < 2; mi++) {
                const int row0 = q0 + wm + mi * 16 + g;
                #pragma unroll
                for (int nj = 0; nj < 8; nj++) {
                    float2 m0 = *(const float2*)(mask + (size_t)row0 * Tk + kr0 + nj * 8 + t * 2);
                    float2 m1 = *(const float2*)(mask + (size_t)(row0 + 8) * Tk + kr0 + nj * 8 + t * 2);
                    sreg[mi][nj][0] += m0.x; sreg[mi][nj][1] += m0.y;
                    sreg[mi][nj][2] += m1.x; sreg[mi][nj][3] += m1.y;
                }
            }
        } else {
            #pragma unroll
            for (int nj = 0; nj < 8; nj++) {
                float2 mv = *(const float2*)(mask + kr0 + nj * 8 + t * 2);
                #pragma unroll
                for (int mi = 0; mi < 2; mi++) {
                    sreg[mi][nj][0] += mv.x; sreg[mi][nj][1] += mv.y;
                    sreg[mi][nj][2] += mv.x; sreg[mi][nj][3] += mv.y;
                }
            }
        }

        // ---- online softmax (4 row-slots: mi*2 + rr) ----
        #pragma unroll
        for (int mi = 0; mi < 2; mi++)
            #pragma unroll
            for (int rr = 0; rr < 2; rr++) {
                const int r = mi * 2 + rr;
                float tm = -1e30f;
                #pragma unroll
                for (int nj = 0; nj < 8; nj++)
                    tm = fmaxf(tm, fmaxf(sreg[mi][nj][rr * 2], sreg[mi][nj][rr * 2 + 1]));
                tm = fmaxf(tm, __shfl_xor_sync(0xffffffffu, tm, 1));
                tm = fmaxf(tm, __shfl_xor_sync(0xffffffffu, tm, 2));
                float nm = fmaxf(m_run[r], tm);
                float sc = __expf(m_run[r] - nm);
                float rs = 0.f;
                #pragma unroll
                for (int nj = 0; nj < 8; nj++) {
                    float p0 = __expf(sreg[mi][nj][rr * 2] - nm);
                    float p1 = __expf(sreg[mi][nj][rr * 2 + 1] - nm);
                    sreg[mi][nj][rr * 2] = p0; sreg[mi][nj][rr * 2 + 1] = p1;
                    rs += p0 + p1;
                }
                rs += __shfl_xor_sync(0xffffffffu, rs, 1);
                rs += __shfl_xor_sync(0xffffffffu, rs, 2);
                l_run[r] = l_run[r] * sc + rs;
                m_run[r] = nm;
                #pragma unroll
                for (int nj = 0; nj < 8; nj++) {
                    oacc[mi][nj][rr * 2] *= sc;
                    oacc[mi][nj][rr * 2 + 1] *= sc;
                }
            }

        // ---- STS V (split) from rkv ----
        #pragma unroll
        for (int j = 0; j < 8; j++) {
            int idx = tid + j * 128;
            int kr = idx >> 4, dq = idx & 15;
            uint32_t h01, l01, h23, l23;
            split2(rkv[j].x, rkv[j].y, h01, l01); split2(rkv[j].z, rkv[j].w, h23, l23);
            *(uint2*)(Vh + kr * 72 + dq * 4) = make_uint2(h01, h23);
            *(uint2*)(Vh + 4608 + kr * 72 + dq * 4) = make_uint2(l01, l23);
        }
        __syncthreads();   // V ready; all warps past S(c)

        // ---- LDG K chunk c+1 (latency hidden by PV) ----
        if (c + 1 < NCH) {
            const int kn0 = kbase + (c + 1) * 64;
            #pragma unroll
            for (int j = 0; j < 8; j++) {
                int idx = tid + j * 128;
                rkv[j] = *(const float4*)(K + (size_t)(kn0 + (idx >> 4)) * EE + hc + (idx & 15) * 4);
            }
        }

        // ---- O += P @ V ----
        #pragma unroll
        for (int ks = 0; ks < 4; ks++) {
            uint32_t ph[2][4], pl[2][4];
            #pragma unroll
            for (int mi = 0; mi < 2; mi++) {
                split2(sreg[mi][2 * ks][0],     sreg[mi][2 * ks][1],     ph[mi][0], pl[mi][0]);
                split2(sreg[mi][2 * ks][2],     sreg[mi][2 * ks][3],     ph[mi][1], pl[mi][1]);
                split2(sreg[mi][2 * ks + 1][0], sreg[mi][2 * ks + 1][1], ph[mi][2], pl[mi][2]);
                split2(sreg[mi][2 * ks + 1][2], sreg[mi][2 * ks + 1][3], ph[mi][3], pl[mi][3]);
            }
            const int krow = ks * 16 + ((lane >> 3) & 1) * 8 + (lane & 7);
            const int nc0 = ((lane >> 4) & 1) * 8;
            #pragma unroll
            for (int nq = 0; nq < 4; nq++) {
                uint32_t vh4[4], vl4[4];
                __half* vp = Vh + krow * 72 + nq * 16 + nc0;
                LDSM4T(vh4, vp);
                LDSM4T(vl4, vp + 4608);
                #pragma unroll
                for (int mi = 0; mi < 2; mi++)
                    #pragma unroll
                    for (int hb = 0; hb < 2; hb++) {
                        float* od = oacc[mi][nq * 2 + hb];
                        const uint32_t* bh = vh4 + hb * 2;
                        const uint32_t* bl = vl4 + hb * 2;
                        hmma(od, ph[mi], bh);
                        hmma(od, ph[mi], bl);
                        hmma(od, pl[mi], bh);
                    }
            }
        }
    }

    // epilogue: unnormalized partials + (m, l)
    #pragma unroll
    for (int mi = 0; mi < 2; mi++) {
        const int row = q0 + wm + mi * 16 + g;
        #pragma unroll
        for (int nj = 0; nj < 8; nj++) {
            const int col = hc + nj * 8 + t * 2;
            *(float2*)(op + (size_t)row * EE + col) =
                make_float2(oacc[mi][nj][0], oacc[mi][nj][1]);
            *(float2*)(op + (size_t)(row + 8) * EE + col) =
                make_float2(oacc[mi][nj][2], oacc[mi][nj][3]);
        }
        if (t == 0) {
            const size_t base = ((size_t)s * NH + blockIdx.y) * T2;
            ml[(base + row) * 2 + 0] = m_run[mi * 2];
            ml[(base + row) * 2 + 1] = l_run[mi * 2];
            ml[(base + row + 8) * 2 + 0] = m_run[mi * 2 + 1];
            ml[(base + row + 8) * 2 + 1] = l_run[mi * 2 + 1];
        }
    }
}

// ---------------- out = LN(relu(h + a [+ a2])) * g + b ----------------
__global__ __launch_bounds__(128) void add_relu_ln(
    const float* __restrict__ h, const float* __restrict__ a,
    const float* __restrict__ a2,
    const float* __restrict__ g, const float* __restrict__ b,
    float* __restrict__ out)
{
    __shared__ float red[4];
    const int row = blockIdx.x;
    const int tid = threadIdx.x;
    const int c = tid * 4;

    float4 hv = *(const float4*)(h + (size_t)row * EE + c);
    float4 av = *(const float4*)(a + (size_t)row * EE + c);
    if (a2) {
        float4 a2v = *(const float4*)(a2 + (size_t)row * EE + c);
        av.x += a2v.x; av.y += a2v.y; av.z += a2v.z; av.w += a2v.w;
    }
    float v[4] = { fmaxf(hv.x + av.x, 0.f), fmaxf(hv.y + av.y, 0.f),
                   fmaxf(hv.z + av.z, 0.f), fmaxf(hv.w + av.w, 0.f) };

    float s = v[0] + v[1] + v[2] + v[3];
    #pragma unroll
    for (int m = 16; m; m >>= 1) s += __shfl_xor_sync(0xffffffffu, s, m);
    if ((tid & 31) == 0) red[tid >> 5] = s;
    __syncthreads();
    float mean = (red[0] + red[1] + red[2] + red[3]) * (1.f / EE);
    __syncthreads();

    float d = 0.f;
    #pragma unroll
    for (int j = 0; j < 4; j++) { float tt = v[j] - mean; d += tt * tt; }
    #pragma unroll
    for (int m = 16; m; m >>= 1) d += __shfl_xor_sync(0xffffffffu, d, m);
    if ((tid & 31) == 0) red[tid >> 5] = d;
    __syncthreads();
    float var = (red[0] + red[1] + red[2] + red[3]) * (1.f / EE);
    float rstd = rsqrtf(var + 1e-5f);

    float4 gv = *(const float4*)(g + c);
    float4 bv = *(const float4*)(b + c);
    float4 w = make_float4((v[0] - mean) * rstd * gv.x + bv.x,
                           (v[1] - mean) * rstd * gv.y + bv.y,
                           (v[2] - mean) * rstd * gv.z + bv.z,
                           (v[3] - mean) * rstd * gv.w + bv.w);
    *(float4*)(out + (size_t)row * EE + c) = w;
}

// ---------------- launch ----------------
extern "C" void kernel_launch(void* const* d_in, const int* in_sizes, int n_in,
                              void* d_out, int out_size)
{
    (void)in_sizes; (void)n_in; (void)out_size;
    const float* x      = (const float*)d_in[0];
    const float* enc    = (const float*)d_in[1];
    const float* am     = (const float*)d_in[2];
    const float* em     = (const float*)d_in[3];
    const float* k_w    = (const float*)d_in[4];
    const float* k_b    = (const float*)d_in[5];
    const float* v_w    = (const float*)d_in[6];
    const float* v_b    = (const float*)d_in[7];
    const float* sa_q_w = (const float*)d_in[8];  const float* sa_q_b = (const float*)d_in[9];
    const float* sa_k_w = (const float*)d_in[10]; const float* sa_k_b = (const float*)d_in[11];
    const float* sa_v_w = (const float*)d_in[12]; const float* sa_v_b = (const float*)d_in[13];
    const float* sa_o_w = (const float*)d_in[14]; const float* sa_o_b = (const float*)d_in[15];
    const float* n1_g   = (const float*)d_in[16]; const float* n1_b   = (const float*)d_in[17];
    const float* ca_o_w = (const float*)d_in[18]; const float* ca_o_b = (const float*)d_in[19];
    const float* n2_g   = (const float*)d_in[20]; const float* n2_b   = (const float*)d_in[21];
    const float* f1_w   = (const float*)d_in[22]; const float* f1_b   = (const float*)d_in[23];
    const float* f2_w   = (const float*)d_in[24]; const float* f2_b   = (const float*)d_in[25];
    const float* n3_g   = (const float*)d_in[26]; const float* n3_b   = (const float*)d_in[27];

    float *h, *q, *k, *v, *proj, *proj2, *ffn, *Ks, *Vs, *op, *ml, *mlw, *zb;
    cudaGetSymbolAddress((void**)&h,     g_h);
    cudaGetSymbolAddress((void**)&q,     g_q);
    cudaGetSymbolAddress((void**)&k,     g_k);
    cudaGetSymbolAddress((void**)&v,     g_v);
    cudaGetSymbolAddress((void**)&proj,  g_proj);
    cudaGetSymbolAddress((void**)&proj2, g_proj2);
    cudaGetSymbolAddress((void**)&ffn,   g_ffn);
    cudaGetSymbolAddress((void**)&Ks,    g_Ks);
    cudaGetSymbolAddress((void**)&Vs,    g_Vs);
    cudaGetSymbolAddress((void**)&op,    g_op);
    cudaGetSymbolAddress((void**)&ml,    g_ml);
    cudaGetSymbolAddress((void**)&mlw,   g_mlw);
    cudaGetSymbolAddress((void**)&zb,    g_zb);

    cudaFuncSetAttribute((const void*)attn_mma,
                         cudaFuncAttributeMaxDynamicSharedMemorySize, ASMEM);
    cudaFuncSetAttribute((const void*)gemm_mma<0>,
                         cudaFuncAttributeMaxDynamicSharedMemorySize, GSMEM);
    cudaFuncSetAttribute((const void*)gemm_mma<1>,
                         cudaFuncAttributeMaxDynamicSharedMemorySize, GSMEM);

    const dim3 gP (EE / 64, T2 / 128, 1);   // single-output GEMMs
    const dim3 gP3(EE / 64, T2 / 128, 3);   // fused QKV
    const dim3 gP2(EE / 64, T2 / 128, 2);   // fused Ks/Vs and split-K f2
    const dim3 gF (FF / 64, T2 / 128, 1);   // f1
    const dim3 gA (T2 / 128, NH, 2);        // attention split-KV
    const dim3 gW (NH * T2 / 256, 1, 1);    // mlw

    copyk<<<T2 * EE / 1024, 256>>>(x, h);
    gemm_mma<0><<<gP2, 256, GSMEM>>>(enc, nullptr,
        k_w, k_b, Ks, v_w, v_b, Vs, v_w, v_b, Vs, EE, EE, EE, 0, 0);

    for (int l = 0; l < NL; l++) {
        const size_t wo = (size_t)l * EE * EE, bo = (size_t)l * EE;
        // self-attention: fused QKV projections
        gemm_mma<0><<<gP3, 256, GSMEM>>>(h, nullptr,
            sa_q_w + wo, sa_q_b + bo, q,
            sa_k_w + wo, sa_k_b + bo, k,
            sa_v_w + wo, sa_v_b + bo, v, EE, EE, EE, 0, 0);
        attn_mma<<<gA, 128, ASMEM>>>(q, k, v, am, op, ml, T2, 1);
        mlw_kernel<<<gW, 256>>>(ml, mlw);
        gemm_mma<1><<<gP, 256, GSMEM>>>(op, mlw,
            sa_o_w + wo, sa_o_b + bo, proj,
            sa_o_w + wo, sa_o_b + bo, proj,
            sa_o_w + wo, sa_o_b + bo, proj, EE, EE, EE, 0, 1);
        add_relu_ln<<<T2, 128>>>(h, proj, nullptr, n1_g + bo, n1_b + bo, h);
        // cross-attention (Q = h directly, per reference)
        attn_mma<<<gA, 128, ASMEM>>>(h, Ks, Vs, em, op, ml, T1, 0);
        mlw_kernel<<<gW, 256>>>(ml, mlw);
        gemm_mma<1><<<gP, 256, GSMEM>>>(op, mlw,
            ca_o_w + wo, ca_o_b + bo, proj,
            ca_o_w + wo, ca_o_b + bo, proj,
            ca_o_w + wo, ca_o_b + bo, proj, EE, EE, EE, 0, 1);
        add_relu_ln<<<T2, 128>>>(h, proj, nullptr, n2_g + bo, n2_b + bo, h);
        // FFN: f1 full-K, f2 split-K x2 (partials summed in add_relu_ln)
        gemm_mma<0><<<gF, 256, GSMEM>>>(h, nullptr,
            f1_w + (size_t)l * EE * FF, f1_b + (size_t)l * FF, ffn,
            f1_w + (size_t)l * EE * FF, f1_b + (size_t)l * FF, ffn,
            f1_w + (size_t)l * EE * FF, f1_b + (size_t)l * FF, ffn, FF, EE, EE, 0, 1);
        gemm_mma<0><<<gP2, 256, GSMEM>>>(ffn, nullptr,
            f2_w + (size_t)l * FF * EE,                      f2_b + bo, proj,
            f2_w + (size_t)l * FF * EE + (size_t)1024 * EE,  zb,        proj2,
            f2_w + (size_t)l * FF * EE,                      f2_b + bo, proj,
            EE, FF, 1024, 1024, 0);
        add_relu_ln<<<T2, 128>>>(h, proj, proj2, n3_g + bo, n3_b + bo, h);
    }

    copyk<<<T2 * EE / 1024, 256>>>(h, (float*)d_out);
}